// round 2
// baseline (speedup 1.0000x reference)
#include <cuda_runtime.h>
#include <cuda_bf16.h>

#define BB 8
#define FF 128
#define PP 256
#define TT 2048
#define T_TILE 128
#define NTILE (TT / T_TILE)   // 16
#define P_TILE 32

// scratch (allocation-free per harness rules)
__device__ float g_tb[BB * FF];
__device__ float g_cs[BB * FF];
__device__ int   g_list[BB * NTILE * FF];
__device__ int   g_cnt[BB * NTILE];

// ---------------- prep: per-flash center/normalization + per-tile flash lists ----
__global__ __launch_bounds__(FF)
void flash_prep_kernel(const float* __restrict__ ftime,
                       const float* __restrict__ conf,
                       const float* __restrict__ sigma_ptr)
{
    const int b = blockIdx.x;
    const int f = threadIdx.x;

    const float sigma = sigma_ptr ? __ldg(sigma_ptr) : 1.0f;
    const float inv_s = 1.0f / sigma;
    const float W     = 10.0f * sigma;   // exp(-50) ~ 2e-22 relative: negligible

    float tb = fminf(fmaxf(__ldg(&ftime[b * FF + f]) * (float)TT, 0.0f),
                     (float)(TT - 1));
    int lo = max(0, (int)ceilf(tb - W));
    int hi = min(TT - 1, (int)floorf(tb + W));
    float s = 0.0f;
    for (int t = lo; t <= hi; ++t) {
        float z = ((float)t - tb) * inv_s;
        s += __expf(-0.5f * z * z);
    }
    g_tb[b * FF + f] = tb;
    g_cs[b * FF + f] = __ldg(&conf[b * FF + f]) / (s + 1e-10f);

    __shared__ float s_tb[FF];
    s_tb[f] = tb;
    __syncthreads();

    // deterministic per-tile compaction: 4 warps cover 16 tiles
    const int warp = f >> 5, lane = f & 31;
    for (int tile = warp; tile < NTILE; tile += 4) {
        const float tlo = (float)(tile * T_TILE) - W;
        const float thi = (float)(tile * T_TILE + T_TILE - 1) + W;
        int cnt = 0;
        int* lst = &g_list[(b * NTILE + tile) * FF];
        #pragma unroll
        for (int base = 0; base < FF; base += 32) {
            const int ff  = base + lane;
            const float v = s_tb[ff];
            const bool rel = (v >= tlo) && (v <= thi);
            unsigned m = __ballot_sync(0xffffffffu, rel);
            if (rel) lst[cnt + __popc(m & ((1u << lane) - 1u))] = ff;
            cnt += __popc(m);
        }
        if (lane == 0) g_cnt[b * NTILE + tile] = cnt;
    }
}

// ---------------- main: banded accumulation with packed f32x2 FMAs ----------------
__global__ __launch_bounds__(T_TILE)
void flash_reco_kernel(const float* __restrict__ pe,   // [B,F,P]
                       const float* __restrict__ sigma_ptr,
                       float* __restrict__ out)        // [B,P,T]
{
    const int tid  = threadIdx.x;
    const int b    = blockIdx.z;
    const int p0   = blockIdx.y * P_TILE;
    const int tile = blockIdx.x;
    const int t0   = tile * T_TILE;

    const float sigma = sigma_ptr ? __ldg(sigma_ptr) : 1.0f;
    const float inv_s = 1.0f / sigma;
    const float t_f   = (float)(t0 + tid);

    const int  cnt = __ldg(&g_cnt[b * NTILE + tile]);      // uniform per block
    const int* lst = &g_list[(b * NTILE + tile) * FF];

    unsigned long long acc[P_TILE / 2];                    // 16 packed f32x2
    #pragma unroll
    for (int j = 0; j < P_TILE / 2; ++j) acc[j] = 0ull;

    for (int k = 0; k < cnt; ++k) {
        const int   f  = __ldg(&lst[k]);                   // uniform broadcast
        const float tb = __ldg(&g_tb[b * FF + f]);
        const float cs = __ldg(&g_cs[b * FF + f]);
        const float z  = (t_f - tb) * inv_s;
        const float w  = cs * __expf(-0.5f * z * z);       // underflows to 0 far out
        unsigned long long ww;
        asm("mov.b64 %0, {%1, %1};" : "=l"(ww) : "f"(w));

        const longlong2* pef =
            reinterpret_cast<const longlong2*>(pe + (b * FF + f) * PP + p0);
        #pragma unroll
        for (int q = 0; q < P_TILE / 4; ++q) {
            longlong2 v = __ldg(&pef[q]);                  // LDG.128 broadcast
            asm("fma.rn.f32x2 %0, %1, %2, %0;"
                : "+l"(acc[2 * q])     : "l"(ww), "l"(v.x));
            asm("fma.rn.f32x2 %0, %1, %2, %0;"
                : "+l"(acc[2 * q + 1]) : "l"(ww), "l"(v.y));
        }
    }

    float* op = out + (size_t)(b * PP + p0) * TT + t0 + tid;
    #pragma unroll
    for (int j = 0; j < P_TILE / 2; ++j) {
        float lo, hi;
        asm("mov.b64 {%0, %1}, %2;" : "=f"(lo), "=f"(hi) : "l"(acc[j]));
        op[(size_t)(2 * j)     * TT] = lo;
        op[(size_t)(2 * j + 1) * TT] = hi;
    }
}

extern "C" void kernel_launch(void* const* d_in, const int* in_sizes, int n_in,
                              void* d_out, int out_size)
{
    const float* pe = (const float*)d_in[0];           // flashes_pe [B,F,P]
    const float* tm = (const float*)d_in[1];           // flashes_time [B,F,1]
    const float* cf = (const float*)d_in[2];           // flashes_confidence [B,F,1]
    const float* sg = (n_in >= 4) ? (const float*)d_in[n_in - 1] : nullptr;  // sigma last

    flash_prep_kernel<<<BB, FF>>>(tm, cf, sg);
    dim3 grid(NTILE, PP / P_TILE, BB);
    flash_reco_kernel<<<grid, T_TILE>>>(pe, sg, (float*)d_out);
}

// round 3
// speedup vs baseline: 1.3824x; 1.3824x over previous
#include <cuda_runtime.h>
#include <cuda_bf16.h>

#define BB 8
#define FF 128
#define PP 256
#define TT 2048
#define T_TILE 128
#define NTILE (TT / T_TILE)   // 16
#define P_TILE 32

// scratch (allocation-free per harness rules)
__device__ float2 g_meta[BB * FF];          // (tb, cs)
__device__ int    g_list[BB * NTILE * FF];
__device__ int    g_cnt[BB * NTILE];

// ---------------- prep: per-flash center/normalization + per-tile flash lists ----
__global__ __launch_bounds__(FF)
void flash_prep_kernel(const float* __restrict__ ftime,
                       const float* __restrict__ conf,
                       const float* __restrict__ sigma_ptr)
{
    const int b = blockIdx.x;
    const int f = threadIdx.x;

    const float sigma = sigma_ptr ? __ldg(sigma_ptr) : 1.0f;
    const float inv_s = 1.0f / sigma;
    const float W     = 10.0f * sigma;   // exp(-50) ~ 2e-22 relative: negligible

    float tb = fminf(fmaxf(__ldg(&ftime[b * FF + f]) * (float)TT, 0.0f),
                     (float)(TT - 1));
    int lo = max(0, (int)ceilf(tb - W));
    int hi = min(TT - 1, (int)floorf(tb + W));
    float s = 0.0f;
    for (int t = lo; t <= hi; ++t) {
        float z = ((float)t - tb) * inv_s;
        s += __expf(-0.5f * z * z);
    }
    g_meta[b * FF + f] =
        make_float2(tb, __ldg(&conf[b * FF + f]) / (s + 1e-10f));

    __shared__ float s_tb[FF];
    s_tb[f] = tb;
    __syncthreads();

    // deterministic per-tile compaction: 4 warps cover 16 tiles
    const int warp = f >> 5, lane = f & 31;
    for (int tile = warp; tile < NTILE; tile += 4) {
        const float tlo = (float)(tile * T_TILE) - W;
        const float thi = (float)(tile * T_TILE + T_TILE - 1) + W;
        int cnt = 0;
        int* lst = &g_list[(b * NTILE + tile) * FF];
        #pragma unroll
        for (int base = 0; base < FF; base += 32) {
            const int ff  = base + lane;
            const float v = s_tb[ff];
            const bool rel = (v >= tlo) && (v <= thi);
            unsigned m = __ballot_sync(0xffffffffu, rel);
            if (rel) lst[cnt + __popc(m & ((1u << lane) - 1u))] = ff;
            cnt += __popc(m);
        }
        if (lane == 0) g_cnt[b * NTILE + tile] = cnt;
    }
}

// ---------------- main: shared-staged banded accumulation ------------------------
__global__ __launch_bounds__(T_TILE)
void flash_reco_kernel(const float* __restrict__ pe,   // [B,F,P]
                       const float* __restrict__ sigma_ptr,
                       float* __restrict__ out)        // [B,P,T]
{
    __shared__ float2 s_meta[FF];                 // (tb, cs) per relevant flash
    __shared__ float4 s_pe[FF][P_TILE / 4];       // 32 floats per relevant flash

    const int tid  = threadIdx.x;
    const int b    = blockIdx.z;
    const int p0   = blockIdx.y * P_TILE;
    const int tile = blockIdx.x;
    const int t0   = tile * T_TILE;

    const float sigma = sigma_ptr ? __ldg(sigma_ptr) : 1.0f;
    const float inv_s = 1.0f / sigma;
    const float t_f   = (float)(t0 + tid);

    const int  cnt = __ldg(&g_cnt[b * NTILE + tile]);    // uniform per block
    const int* lst = &g_list[(b * NTILE + tile) * FF];

    // ---- parallel staging burst: all loads independent, one round-trip ----
    for (int k = tid; k < cnt; k += T_TILE)              // <=1 iter typically
        s_meta[k] = __ldg(&g_meta[b * FF + __ldg(&lst[k])]);
    for (int i = tid; i < cnt * (P_TILE / 4); i += T_TILE) {  // <=1 iter typically
        const int k = i >> 3, q = i & 7;
        const int f = __ldg(&lst[k]);
        s_pe[k][q] = __ldg(reinterpret_cast<const float4*>(
                               pe + (b * FF + f) * PP + p0) + q);
    }
    __syncthreads();

    // ---- on-chip inner loop: LDS + expf + packed FMA only ----
    unsigned long long acc[P_TILE / 2];                  // 16 packed f32x2
    #pragma unroll
    for (int j = 0; j < P_TILE / 2; ++j) acc[j] = 0ull;

    #pragma unroll 2
    for (int k = 0; k < cnt; ++k) {
        const float2 m = s_meta[k];                      // LDS.64 broadcast
        const float  z = (t_f - m.x) * inv_s;
        const float  w = m.y * __expf(-0.5f * z * z);
        unsigned long long ww;
        asm("mov.b64 %0, {%1, %1};" : "=l"(ww) : "f"(w));

        const ulonglong2* row =
            reinterpret_cast<const ulonglong2*>(&s_pe[k][0]);
        #pragma unroll
        for (int q = 0; q < P_TILE / 4; ++q) {
            ulonglong2 v = row[q];                       // LDS.128 broadcast
            asm("fma.rn.f32x2 %0, %1, %2, %0;"
                : "+l"(acc[2 * q])     : "l"(ww), "l"(v.x));
            asm("fma.rn.f32x2 %0, %1, %2, %0;"
                : "+l"(acc[2 * q + 1]) : "l"(ww), "l"(v.y));
        }
    }

    // ---- coalesced stores (threads span contiguous t) ----
    float* op = out + (size_t)(b * PP + p0) * TT + t0 + tid;
    #pragma unroll
    for (int j = 0; j < P_TILE / 2; ++j) {
        float lo, hi;
        asm("mov.b64 {%0, %1}, %2;" : "=f"(lo), "=f"(hi) : "l"(acc[j]));
        op[(size_t)(2 * j)     * TT] = lo;
        op[(size_t)(2 * j + 1) * TT] = hi;
    }
}

extern "C" void kernel_launch(void* const* d_in, const int* in_sizes, int n_in,
                              void* d_out, int out_size)
{
    const float* pe = (const float*)d_in[0];           // flashes_pe [B,F,P]
    const float* tm = (const float*)d_in[1];           // flashes_time [B,F,1]
    const float* cf = (const float*)d_in[2];           // flashes_confidence [B,F,1]
    const float* sg = (n_in >= 4) ? (const float*)d_in[n_in - 1] : nullptr;  // sigma last

    flash_prep_kernel<<<BB, FF>>>(tm, cf, sg);
    dim3 grid(NTILE, PP / P_TILE, BB);
    flash_reco_kernel<<<grid, T_TILE>>>(pe, sg, (float*)d_out);
}

// round 4
// speedup vs baseline: 1.8889x; 1.3664x over previous
#include <cuda_runtime.h>
#include <cuda_bf16.h>

#define BB 8
#define FF 128
#define PP 256
#define TT 2048
#define T_TILE 128
#define NTILE (TT / T_TILE)   // 16
#define P_TILE 32
#define MAXREL 64             // staged flashes per block (cnt ~9 expected)

__global__ __launch_bounds__(T_TILE)
void flash_reco_kernel(const float* __restrict__ pe,     // [B,F,P]
                       const float* __restrict__ ftime,  // [B,F]
                       const float* __restrict__ conf,   // [B,F]
                       const float* __restrict__ sigma_ptr,
                       float* __restrict__ out)          // [B,P,T]
{
    __shared__ float  s_conf[FF];
    __shared__ float2 s_meta[MAXREL];            // (tb, cs)
    __shared__ int    s_idx[FF];                 // compacted flash ids (f-ordered)
    __shared__ float4 s_pe[MAXREL][P_TILE / 4];  // staged pe rows
    __shared__ int    s_wcnt[4];

    const int tid  = threadIdx.x;
    const int b    = blockIdx.z;
    const int p0   = blockIdx.y * P_TILE;
    const int t0   = blockIdx.x * T_TILE;

    const float sigma = sigma_ptr ? __ldg(sigma_ptr) : 1.0f;
    const float inv_s = 1.0f / sigma;
    const float W     = 10.0f * sigma;   // exp(-50) ~ 2e-22 relative: negligible

    // ---- Phase A: per-flash center + relevance compaction (f = tid) ----
    {
        const int f = tid;
        s_conf[f] = __ldg(&conf[b * FF + f]);    // independent, overlaps below
        float tb = fminf(fmaxf(__ldg(&ftime[b * FF + f]) * (float)TT, 0.0f),
                         (float)(TT - 1));
        bool rel = (tb >= (float)t0 - W) && (tb <= (float)(t0 + T_TILE - 1) + W);
        unsigned m = __ballot_sync(0xffffffffu, rel);
        int warp = f >> 5, lane = f & 31;
        if (lane == 0) s_wcnt[warp] = __popc(m);
        __syncthreads();
        int off = 0;
        #pragma unroll
        for (int wp = 0; wp < 4; ++wp)
            if (wp < warp) off += s_wcnt[wp];
        if (rel) {
            int pos = off + __popc(m & ((1u << lane) - 1u));
            s_idx[pos] = f;
            if (pos < MAXREL) s_meta[pos] = make_float2(tb, 0.0f);
        }
    }
    __syncthreads();
    const int cnt  = s_wcnt[0] + s_wcnt[1] + s_wcnt[2] + s_wcnt[3];
    const int cstg = min(cnt, MAXREL);

    // ---- Phase B: stage pe rows (parallel burst) + cooperative normalizers ----
    for (int i = tid; i < cstg * (P_TILE / 4); i += T_TILE) {
        const int k = i >> 3, q = i & 7;
        s_pe[k][q] = __ldg(reinterpret_cast<const float4*>(
                               pe + (b * FF + s_idx[k]) * PP + p0) + q);
    }
    {   // warp w owns compacted flash k = w, w+4, ... ; lanes spread the window
        const int warp = tid >> 5, lane = tid & 31;
        for (int k = warp; k < cstg; k += 4) {
            const float tb = s_meta[k].x;
            int lo = max(0, (int)ceilf(tb - W));
            int hi = min(TT - 1, (int)floorf(tb + W));
            float s = 0.0f;
            for (int t = lo + lane; t <= hi; t += 32) {
                float z = ((float)t - tb) * inv_s;
                s += __expf(-0.5f * z * z);
            }
            #pragma unroll
            for (int d = 16; d > 0; d >>= 1)
                s += __shfl_xor_sync(0xffffffffu, s, d);
            if (lane == 0)
                s_meta[k].y = s_conf[s_idx[k]] / (s + 1e-10f);
        }
    }
    __syncthreads();

    // ---- Phase C: banded accumulation, warp-uniform flash skip ----
    const float t_f = (float)(t0 + tid);
    const float wlo = (float)(t0 + (tid & ~31)) - W;         // warp-uniform
    const float whi = wlo + 31.0f + 2.0f * W;

    unsigned long long acc[P_TILE / 2];                      // 16 packed f32x2
    #pragma unroll
    for (int j = 0; j < P_TILE / 2; ++j) acc[j] = 0ull;

    for (int k = 0; k < cstg; ++k) {
        const float2 m = s_meta[k];                          // LDS.64 broadcast
        if (m.x < wlo || m.x > whi) continue;                // warp-uniform branch
        const float z = (t_f - m.x) * inv_s;
        const float w = m.y * __expf(-0.5f * z * z);
        unsigned long long ww;
        asm("mov.b64 %0, {%1, %1};" : "=l"(ww) : "f"(w));
        const ulonglong2* row = reinterpret_cast<const ulonglong2*>(&s_pe[k][0]);
        #pragma unroll
        for (int q = 0; q < P_TILE / 4; ++q) {
            ulonglong2 v = row[q];                           // LDS.128 broadcast
            asm("fma.rn.f32x2 %0, %1, %2, %0;" : "+l"(acc[2*q])   : "l"(ww), "l"(v.x));
            asm("fma.rn.f32x2 %0, %1, %2, %0;" : "+l"(acc[2*q+1]) : "l"(ww), "l"(v.y));
        }
    }

    // overflow fallback (cnt > MAXREL): global path, effectively never taken
    for (int k = MAXREL; k < cnt; ++k) {
        const int f = s_idx[k];
        float tb = fminf(fmaxf(__ldg(&ftime[b * FF + f]) * (float)TT, 0.0f),
                         (float)(TT - 1));
        if (tb < wlo || tb > whi) continue;
        int lo = max(0, (int)ceilf(tb - W));
        int hi = min(TT - 1, (int)floorf(tb + W));
        float s = 0.0f;
        for (int t = lo; t <= hi; ++t) {
            float zz = ((float)t - tb) * inv_s;
            s += __expf(-0.5f * zz * zz);
        }
        const float z = (t_f - tb) * inv_s;
        const float w = (s_conf[f] / (s + 1e-10f)) * __expf(-0.5f * z * z);
        unsigned long long ww;
        asm("mov.b64 %0, {%1, %1};" : "=l"(ww) : "f"(w));
        const ulonglong2* row =
            reinterpret_cast<const ulonglong2*>(pe + (b * FF + f) * PP + p0);
        #pragma unroll
        for (int q = 0; q < P_TILE / 4; ++q) {
            ulonglong2 v = __ldg(&row[q]);
            asm("fma.rn.f32x2 %0, %1, %2, %0;" : "+l"(acc[2*q])   : "l"(ww), "l"(v.x));
            asm("fma.rn.f32x2 %0, %1, %2, %0;" : "+l"(acc[2*q+1]) : "l"(ww), "l"(v.y));
        }
    }

    // ---- Phase D: coalesced stores (threads span contiguous t) ----
    float* op = out + (size_t)(b * PP + p0) * TT + t0 + tid;
    #pragma unroll
    for (int j = 0; j < P_TILE / 2; ++j) {
        float lo, hi;
        asm("mov.b64 {%0, %1}, %2;" : "=f"(lo), "=f"(hi) : "l"(acc[j]));
        op[(size_t)(2 * j)     * TT] = lo;
        op[(size_t)(2 * j + 1) * TT] = hi;
    }
}

extern "C" void kernel_launch(void* const* d_in, const int* in_sizes, int n_in,
                              void* d_out, int out_size)
{
    const float* pe = (const float*)d_in[0];           // flashes_pe [B,F,P]
    const float* tm = (const float*)d_in[1];           // flashes_time [B,F,1]
    const float* cf = (const float*)d_in[2];           // flashes_confidence [B,F,1]
    const float* sg = (n_in >= 4) ? (const float*)d_in[n_in - 1] : nullptr;  // sigma last

    dim3 grid(NTILE, PP / P_TILE, BB);
    flash_reco_kernel<<<grid, T_TILE>>>(pe, tm, cf, sg, (float*)d_out);
}

// round 5
// speedup vs baseline: 1.9354x; 1.0246x over previous
#include <cuda_runtime.h>
#include <cuda_bf16.h>

#define BB 8
#define FF 128
#define PP 256
#define TT 2048
#define T_TILE 64
#define NTILE (TT / T_TILE)    // 32
#define P_TILE 32              // per block; 16 per thread-group
#define MAXREL 32              // staged flashes per block (expected ~5)

__global__ __launch_bounds__(128)
void flash_reco_kernel(const float* __restrict__ pe,     // [B,F,P]
                       const float* __restrict__ ftime,  // [B,F]
                       const float* __restrict__ conf,   // [B,F]
                       const float* __restrict__ sigma_ptr,
                       float* __restrict__ out)          // [B,P,T]
{
    __shared__ float2 s_meta[MAXREL];            // (tb, cs)
    __shared__ int    s_idx[FF];                 // compacted flash ids (f-ordered)
    __shared__ float  s_pe[MAXREL][P_TILE];      // staged pe rows (32 floats each)
    __shared__ int    s_wcnt[4];

    const int tid  = threadIdx.x;
    const int b    = blockIdx.z;
    const int p0   = blockIdx.y * P_TILE;
    const int t0   = blockIdx.x * T_TILE;

    const float sigma = sigma_ptr ? __ldg(sigma_ptr) : 1.0f;
    const float inv_s = 1.0f / sigma;
    const float W     = 10.0f * sigma;   // exp(-50) ~ 2e-22 relative: negligible

    // ---- Phase A: per-flash center + relevance compaction (f = tid) ----
    {
        const int f = tid;
        float tb = fminf(fmaxf(__ldg(&ftime[b * FF + f]) * (float)TT, 0.0f),
                         (float)(TT - 1));
        bool rel = (tb >= (float)t0 - W) && (tb <= (float)(t0 + T_TILE - 1) + W);
        unsigned m = __ballot_sync(0xffffffffu, rel);
        int warp = tid >> 5, lane = tid & 31;
        if (lane == 0) s_wcnt[warp] = __popc(m);
        __syncthreads();
        int off = 0;
        #pragma unroll
        for (int wp = 0; wp < 4; ++wp)
            if (wp < warp) off += s_wcnt[wp];
        if (rel) {
            int pos = off + __popc(m & ((1u << lane) - 1u));
            s_idx[pos] = f;
            if (pos < MAXREL) s_meta[pos] = make_float2(tb, 0.0f);
        }
    }
    __syncthreads();
    const int cnt  = s_wcnt[0] + s_wcnt[1] + s_wcnt[2] + s_wcnt[3];
    const int cstg = min(cnt, MAXREL);

    // ---- Phase B: stage pe rows (parallel burst) + normalizers ----
    for (int i = tid; i < cstg * (P_TILE / 4); i += 128) {  // float4 granularity
        const int k = i >> 3, q = i & 7;
        reinterpret_cast<float4*>(&s_pe[k][0])[q] =
            __ldg(reinterpret_cast<const float4*>(
                      pe + (b * FF + s_idx[k]) * PP + p0) + q);
    }
    if (tid < cstg) {
        const int   k  = tid;
        const float tb = s_meta[k].x;
        const float cf = __ldg(&conf[b * FF + s_idx[k]]);
        float s;
        if (sigma >= 0.9f && tb >= W && tb <= (float)(TT - 1) - W) {
            s = sigma * 2.5066282746310002f;      // sqrt(2*pi)*sigma, theta corr < 3e-9
        } else {
            int lo = max(0, (int)ceilf(tb - W));
            int hi = min(TT - 1, (int)floorf(tb + W));
            s = 0.0f;
            for (int t = lo; t <= hi; ++t) {
                float z = ((float)t - tb) * inv_s;
                s += __expf(-0.5f * z * z);
            }
        }
        s_meta[k].y = cf / (s + 1e-10f);
    }
    __syncthreads();

    // ---- Phase C: per-warp register compaction + banded accumulation ----
    // thread -> (t, 16 p's): t index = tid & 63; p group = tid >> 6
    const int   ti   = tid & 63;
    const float t_f  = (float)(t0 + ti);
    const int   pb   = p0 + (tid >> 6) * 16;
    const float wlo  = (float)(t0 + (ti & 32)) - W;          // warp t-base
    const float whi  = wlo + 31.0f + 2.0f * W;

    unsigned long long acc[8];                               // 8 packed f32x2 = 16 p
    #pragma unroll
    for (int j = 0; j < 8; ++j) acc[j] = 0ull;

    {
        const int lane = tid & 31;
        bool r = false;
        if (lane < cstg) {
            float tbl = s_meta[lane].x;
            r = (tbl >= wlo) && (tbl <= whi);
        }
        unsigned mask = __ballot_sync(0xffffffffu, r);
        while (mask) {                                       // ascending k: deterministic
            const int k = __ffs(mask) - 1;
            mask &= mask - 1;
            const float2 m = s_meta[k];                      // LDS.64 broadcast
            const float  z = (t_f - m.x) * inv_s;
            const float  w = m.y * __expf(-0.5f * z * z);
            unsigned long long ww;
            asm("mov.b64 %0, {%1, %1};" : "=l"(ww) : "f"(w));
            const ulonglong2* row =
                reinterpret_cast<const ulonglong2*>(&s_pe[k][(tid >> 6) * 16]);
            #pragma unroll
            for (int q = 0; q < 4; ++q) {
                ulonglong2 v = row[q];                       // LDS.128 broadcast
                asm("fma.rn.f32x2 %0, %1, %2, %0;" : "+l"(acc[2*q])   : "l"(ww), "l"(v.x));
                asm("fma.rn.f32x2 %0, %1, %2, %0;" : "+l"(acc[2*q+1]) : "l"(ww), "l"(v.y));
            }
        }
    }

    // overflow fallback (cnt > MAXREL): global path, effectively never taken
    for (int k = MAXREL; k < cnt; ++k) {
        const int f = s_idx[k];
        float tb = fminf(fmaxf(__ldg(&ftime[b * FF + f]) * (float)TT, 0.0f),
                         (float)(TT - 1));
        if (tb < wlo || tb > whi) continue;
        int lo = max(0, (int)ceilf(tb - W));
        int hi = min(TT - 1, (int)floorf(tb + W));
        float s = 0.0f;
        for (int t = lo; t <= hi; ++t) {
            float zz = ((float)t - tb) * inv_s;
            s += __expf(-0.5f * zz * zz);
        }
        const float z = (t_f - tb) * inv_s;
        const float w = (__ldg(&conf[b * FF + f]) / (s + 1e-10f)) * __expf(-0.5f * z * z);
        unsigned long long ww;
        asm("mov.b64 %0, {%1, %1};" : "=l"(ww) : "f"(w));
        const ulonglong2* row =
            reinterpret_cast<const ulonglong2*>(pe + (b * FF + f) * PP + pb);
        #pragma unroll
        for (int q = 0; q < 4; ++q) {
            ulonglong2 v = __ldg(&row[q]);
            asm("fma.rn.f32x2 %0, %1, %2, %0;" : "+l"(acc[2*q])   : "l"(ww), "l"(v.x));
            asm("fma.rn.f32x2 %0, %1, %2, %0;" : "+l"(acc[2*q+1]) : "l"(ww), "l"(v.y));
        }
    }

    // ---- Phase D: coalesced stores (lanes span contiguous t) ----
    float* op = out + (size_t)(b * PP + pb) * TT + t0 + ti;
    #pragma unroll
    for (int j = 0; j < 8; ++j) {
        float lo, hi;
        asm("mov.b64 {%0, %1}, %2;" : "=f"(lo), "=f"(hi) : "l"(acc[j]));
        op[(size_t)(2 * j)     * TT] = lo;
        op[(size_t)(2 * j + 1) * TT] = hi;
    }
}

extern "C" void kernel_launch(void* const* d_in, const int* in_sizes, int n_in,
                              void* d_out, int out_size)
{
    const float* pe = (const float*)d_in[0];           // flashes_pe [B,F,P]
    const float* tm = (const float*)d_in[1];           // flashes_time [B,F,1]
    const float* cf = (const float*)d_in[2];           // flashes_confidence [B,F,1]
    const float* sg = (n_in >= 4) ? (const float*)d_in[n_in - 1] : nullptr;  // sigma last

    dim3 grid(NTILE, PP / P_TILE, BB);                 // 32 x 8 x 8 = 2048 blocks
    flash_reco_kernel<<<grid, 128>>>(pe, tm, cf, sg, (float*)d_out);
}